// round 15
// baseline (speedup 1.0000x reference)
#include <cuda_runtime.h>

#define KS 48
#define NT 256

typedef unsigned long long ull;

// strides (floats)
constexpr int SX_STRIDE  = 50;   // X[c][h]
constexpr int W_STRIDE   = 65;   // W[o][c]
constexpr int QKV_STRIDE = 49;   // QKV[o][h]
constexpr int REL_STRIDE = 97;   // rel[c][d]
constexpr int QK_STRIDE  = 50;   // QR/KR [48][50]  (even: ull loads)
constexpr int SIM_STRIDE = 51;   // SIM   [48][51]

constexpr int QK_G  = 48 * QK_STRIDE + 16;  // 2416
constexpr int SIM_G = 48 * SIM_STRIDE;      // 2448

constexpr int OFF_QKV = 0;
constexpr int OFF_REL = OFF_QKV + 128 * QKV_STRIDE;
constexpr int OFF_PAR = OFF_REL + 16 * REL_STRIDE;
constexpr int OFF_SCR = OFF_PAR + 6 * 48;
constexpr int OFF_X   = OFF_SCR;
constexpr int OFF_W   = OFF_X + 64 * SX_STRIDE;
constexpr int OFF_QR  = OFF_SCR;
constexpr int OFF_KR  = OFF_QR + 2 * QK_G;
constexpr int OFF_SIM = OFF_KR + 2 * QK_G;
constexpr int SCR_FLOATS  = 4 * QK_G + 2 * SIM_G;        // 14560 > 11520
constexpr int SMEM_FLOATS = OFF_SCR + SCR_FLOATS;        // 22672
constexpr int SMEM_BYTES  = SMEM_FLOATS * 4;             // 90688 B -> 2 CTAs/SM

constexpr int OUT_PLANE_STRIDE = KS * KS * 64;

__device__ __forceinline__ ull dupf(float v) {
    ull r; unsigned u = __float_as_uint(v);
    asm("mov.b64 %0, {%1, %1};" : "=l"(r) : "r"(u));
    return r;
}
__device__ __forceinline__ void ffma2(ull& d, ull a, ull b) {
    asm("fma.rn.f32x2 %0, %1, %2, %0;" : "+l"(d) : "l"(a), "l"(b));
}
__device__ __forceinline__ float f2lo(ull v) { return __uint_as_float((unsigned)(v & 0xffffffffull)); }
__device__ __forceinline__ float f2hi(ull v) { return __uint_as_float((unsigned)(v >> 32)); }

__global__ void __launch_bounds__(NT, 2) axial_kernel(
    const float* __restrict__ x,      const float* __restrict__ w_qkv,
    const float* __restrict__ relv,
    const float* __restrict__ g_qkv,  const float* __restrict__ b_qkv,
    const float* __restrict__ g_sim,  const float* __restrict__ b_sim,
    const float* __restrict__ g_out,  const float* __restrict__ b_out,
    float* __restrict__ out)
{
    extern __shared__ float sm[];
    float* sX   = sm + OFF_X;
    float* sW   = sm + OFF_W;
    float* sQKV = sm + OFF_QKV;
    float* sRel = sm + OFF_REL;
    float* sGQ  = sm + OFF_PAR;
    float* sBQ  = sGQ + 48; float* sGS = sBQ + 48; float* sBS = sGS + 48;
    float* sGO  = sBS + 48; float* sBO = sGO + 48;

    const int tid = threadIdx.x;
    const int blk = blockIdx.x;
    const int wi = blk / KS, li = blk % KS;

    // ---- load X (as [c][h]), W, relative, BN params ----
    for (int idx = tid; idx < KS * 64; idx += NT) {
        const int h = idx >> 6, c = idx & 63;
        sX[c * SX_STRIDE + h] = x[((h * KS + wi) * KS + li) * 64 + c];
    }
    for (int idx = tid; idx < 128 * 64; idx += NT)
        sW[(idx >> 6) * W_STRIDE + (idx & 63)] = w_qkv[idx];
    for (int idx = tid; idx < 16 * 95; idx += NT)
        sRel[(idx / 95) * REL_STRIDE + (idx % 95)] = relv[idx];
    if (tid < KS) {
        const float inv = rsqrtf(1.001f);
        sGQ[tid] = g_qkv[tid] * inv; sBQ[tid] = b_qkv[tid];
        sGS[tid] = g_sim[tid] * inv; sBS[tid] = 3.0f * b_sim[tid];
        sGO[tid] = g_out[tid] * inv; sBO[tid] = 2.0f * b_out[tid];
    }
    __syncthreads();

    // ---- QKV = BN(W @ X): 128x48, 8o x 6h tiles on 128 threads ----
    if (tid < 128) {
        const int o0 = (tid >> 3) * 8;
        const int h0 = (tid & 7) * 6;
        ull a[8][3];
        #pragma unroll
        for (int q = 0; q < 8; ++q)
            #pragma unroll
            for (int p = 0; p < 3; ++p) a[q][p] = 0ull;
        const float* xrow = sX + h0;
        #pragma unroll 2
        for (int c = 0; c < 64; ++c) {
            const ull* xp = reinterpret_cast<const ull*>(xrow + c * SX_STRIDE);
            const ull x01 = xp[0], x23 = xp[1], x45 = xp[2];
            #pragma unroll
            for (int q = 0; q < 8; ++q) {
                const ull wd = dupf(sW[(o0 + q) * W_STRIDE + c]);
                ffma2(a[q][0], wd, x01);
                ffma2(a[q][1], wd, x23);
                ffma2(a[q][2], wd, x45);
            }
        }
        float gg[6], bb[6];
        #pragma unroll
        for (int p = 0; p < 6; ++p) { gg[p] = sGQ[h0 + p]; bb[p] = sBQ[h0 + p]; }
        #pragma unroll
        for (int q = 0; q < 8; ++q) {
            float* dst = sQKV + (o0 + q) * QKV_STRIDE + h0;
            #pragma unroll
            for (int p = 0; p < 3; ++p) {
                dst[2 * p]     = f2lo(a[q][p]) * gg[2 * p]     + bb[2 * p];
                dst[2 * p + 1] = f2hi(a[q][p]) * gg[2 * p + 1] + bb[2 * p + 1];
            }
        }
    }
    __syncthreads();

    // ---- 4 passes, 2 groups each (3 barriers per pass) ----
    for (int gp = 0; gp < 8; gp += 2) {

        // == qr/kr: 2304 quad-tasks, scattered-i (conflict-free rel windows) ==
        for (int q = tid; q < 2304; q += NT) {
            if (q < 1152) {
                const int grp = q / 576; const int r = q - grp * 576;
                const int m = r / 12, il = r % 12;
                const float* Q = sQKV + (16 * (gp + grp)) * QKV_STRIDE;
                float* QRg = sm + OFF_QR + grp * QK_G;
                float a0 = 0.f, a1 = 0.f, a2 = 0.f, a3 = 0.f;
                #pragma unroll
                for (int c = 0; c < 4; ++c) {
                    const float qc = Q[c * QKV_STRIDE + m];
                    const float* rl = sRel + c * REL_STRIDE + (m - il + 47);
                    a0 += qc * rl[0];   a1 += qc * rl[-12];
                    a2 += qc * rl[-24]; a3 += qc * rl[-36];
                }
                float* d = QRg + m * QK_STRIDE + il;
                d[0] = a0; d[12] = a1; d[24] = a2; d[36] = a3;
            } else {
                int r = q - 1152; const int grp = r / 576; r -= grp * 576;
                const int j = r / 12, ml = r % 12;
                const float* Kp = sQKV + (16 * (gp + grp) + 4) * QKV_STRIDE;
                float* KRg = sm + OFF_KR + grp * QK_G;
                float a0 = 0.f, a1 = 0.f, a2 = 0.f, a3 = 0.f;
                #pragma unroll
                for (int c = 0; c < 4; ++c) {
                    const float kc = Kp[c * QKV_STRIDE + j];
                    const float* rl = sRel + (4 + c) * REL_STRIDE + (j - ml + 47);
                    a0 += kc * rl[0];   a1 += kc * rl[-12];
                    a2 += kc * rl[-24]; a3 += kc * rl[-36];
                }
                KRg[ml * QK_STRIDE + j]        = a0;
                KRg[(ml + 12) * QK_STRIDE + j] = a1;
                KRg[(ml + 24) * QK_STRIDE + j] = a2;
                KRg[(ml + 36) * QK_STRIDE + j] = a3;
            }
        }
        __syncthreads();

        // == qk: 6i x 8j tiles; parity m-split; bank-disjoint warp map ==
        // warp v: 0 -> i0 set1 x j0 {0,8,16,24}   (16 tiles, full warp)
        //         1 -> i0 set2 x j0 {0,8,16,24}   (16 tiles, full warp)
        //         2 -> i0 set1 x j0 {32,40}       (8 tiles, 16 lanes)
        //         3 -> i0 set2 x j0 {32,40}       (8 tiles, 16 lanes)
        // set1 = {0,12,24,36}, set2 = {6,18,30,42}; mpar adds 50 ≡ 18 mod 32.
        {
            const int lane = tid & 31;
            const int w    = tid >> 5;           // 0..7
            const int grp  = w >> 2;             // 0 or 1
            const int v    = w & 3;
            const int mpar = lane & 1;
            const int r    = lane >> 1;          // 0..15
            const bool active = (v < 2) || (r < 8);
            const int re = (v < 2) ? r : (r & 7);
            const int i0 = 12 * (re & 3) + 6 * (v & 1);
            const int j0 = (v < 2) ? 8 * (re >> 2) : (32 + 8 * (re >> 2));
            const float* QRg = sm + OFF_QR + grp * QK_G;
            const float* KRg = sm + OFF_KR + grp * QK_G;
            float* SIMg = sm + OFF_SIM + grp * SIM_G;

            ull acc[3][8];
            #pragma unroll
            for (int p = 0; p < 3; ++p)
                #pragma unroll
                for (int jj = 0; jj < 8; ++jj) acc[p][jj] = 0ull;

            #pragma unroll 4
            for (int mm = 0; mm < 24; ++mm) {
                const int m = 2 * mm + mpar;
                const float* qp = QRg + m * QK_STRIDE + i0;
                const ull q01 = reinterpret_cast<const ull*>(qp)[0];
                const ull q23 = reinterpret_cast<const ull*>(qp)[1];
                const ull q45 = reinterpret_cast<const ull*>(qp)[2];
                const float* kp = KRg + m * QK_STRIDE + j0;
                const ull k01 = reinterpret_cast<const ull*>(kp)[0];
                const ull k23 = reinterpret_cast<const ull*>(kp)[1];
                const ull k45 = reinterpret_cast<const ull*>(kp)[2];
                const ull k67 = reinterpret_cast<const ull*>(kp)[3];
                const ull kd[8] = {dupf(f2lo(k01)), dupf(f2hi(k01)),
                                   dupf(f2lo(k23)), dupf(f2hi(k23)),
                                   dupf(f2lo(k45)), dupf(f2hi(k45)),
                                   dupf(f2lo(k67)), dupf(f2hi(k67))};
                #pragma unroll
                for (int jj = 0; jj < 8; ++jj) {
                    ffma2(acc[0][jj], q01, kd[jj]);
                    ffma2(acc[1][jj], q23, kd[jj]);
                    ffma2(acc[2][jj], q45, kd[jj]);
                }
            }
            // per-p combine with parity partner (lane^1) + immediate epilogue.
            // ownership: mpar0 writes rows 0..2, mpar1 writes rows 3..5.
            #pragma unroll
            for (int p = 0; p < 3; ++p) {
                float lo8[8], hi8[8];
                #pragma unroll
                for (int jj = 0; jj < 8; ++jj) {
                    const ull other = __shfl_xor_sync(0xffffffffu, acc[p][jj], 1);
                    lo8[jj] = f2lo(acc[p][jj]) + f2lo(other);
                    hi8[jj] = f2hi(acc[p][jj]) + f2hi(other);
                }
                const int rlo = 2 * p, rhi = 2 * p + 1;
                if (active && ((mpar == 0) ? (rlo <= 2) : (rlo >= 3))) {
                    const int i = i0 + rlo;
                    const ull* qrp = reinterpret_cast<const ull*>(QRg + i * QK_STRIDE + j0);
                    const ull* krp = reinterpret_cast<const ull*>(KRg + i * QK_STRIDE + j0);
                    float* srow = SIMg + i * SIM_STRIDE + j0;
                    #pragma unroll
                    for (int u = 0; u < 4; ++u) {
                        const ull qv2 = qrp[u], kv2 = krp[u];
                        const int j = j0 + 2 * u;
                        srow[2 * u]     = (lo8[2 * u]     + f2lo(qv2) + f2lo(kv2)) * sGS[j]     + sBS[j];
                        srow[2 * u + 1] = (lo8[2 * u + 1] + f2hi(qv2) + f2hi(kv2)) * sGS[j + 1] + sBS[j + 1];
                    }
                }
                if (active && ((mpar == 0) ? (rhi <= 2) : (rhi >= 3))) {
                    const int i = i0 + rhi;
                    const ull* qrp = reinterpret_cast<const ull*>(QRg + i * QK_STRIDE + j0);
                    const ull* krp = reinterpret_cast<const ull*>(KRg + i * QK_STRIDE + j0);
                    float* srow = SIMg + i * SIM_STRIDE + j0;
                    #pragma unroll
                    for (int u = 0; u < 4; ++u) {
                        const ull qv2 = qrp[u], kv2 = krp[u];
                        const int j = j0 + 2 * u;
                        srow[2 * u]     = (hi8[2 * u]     + f2lo(qv2) + f2lo(kv2)) * sGS[j]     + sBS[j];
                        srow[2 * u + 1] = (hi8[2 * u + 1] + f2hi(qv2) + f2hi(kv2)) * sGS[j + 1] + sBS[j + 1];
                    }
                }
            }
        }
        __syncthreads();

        // == softmax: 96 rows as 48 pairs; 16 lanes/row, 3 j/lane; 2-wide ILP ==
        {
            const int lane = tid & 31, wp = tid >> 5;
            const int half16 = lane >> 4;
            const int jb = (lane & 15) * 3;
            #pragma unroll
            for (int rp = wp; rp < 48; rp += 16) {
                float* rowA = sm + OFF_SIM + (2 * rp + half16) * SIM_STRIDE;
                float* rowB = sm + OFF_SIM + (2 * (rp + 8) + half16) * SIM_STRIDE;
                const float a0 = rowA[jb], a1 = rowA[jb + 1], a2 = rowA[jb + 2];
                const float b0 = rowB[jb], b1 = rowB[jb + 1], b2 = rowB[jb + 2];
                float mxA = fmaxf(a0, fmaxf(a1, a2));
                float mxB = fmaxf(b0, fmaxf(b1, b2));
                #pragma unroll
                for (int off = 1; off < 16; off <<= 1) {
                    mxA = fmaxf(mxA, __shfl_xor_sync(0xffffffffu, mxA, off));
                    mxB = fmaxf(mxB, __shfl_xor_sync(0xffffffffu, mxB, off));
                }
                const float eA0 = __expf(a0 - mxA), eA1 = __expf(a1 - mxA), eA2 = __expf(a2 - mxA);
                const float eB0 = __expf(b0 - mxB), eB1 = __expf(b1 - mxB), eB2 = __expf(b2 - mxB);
                float sA = eA0 + eA1 + eA2;
                float sB = eB0 + eB1 + eB2;
                #pragma unroll
                for (int off = 1; off < 16; off <<= 1) {
                    sA += __shfl_xor_sync(0xffffffffu, sA, off);
                    sB += __shfl_xor_sync(0xffffffffu, sB, off);
                }
                const float rA = __fdividef(1.0f, sA);
                const float rB = __fdividef(1.0f, sB);
                rowA[jb] = eA0 * rA; rowA[jb + 1] = eA1 * rA; rowA[jb + 2] = eA2 * rA;
                rowB[jb] = eB0 * rB; rowB[jb + 1] = eB1 * rB; rowB[jb + 2] = eB2 * rB;
            }
        }
        __syncthreads();

        // == sv: 4c x 3i tiles x 4 j-splits; rel windows preloaded; STG direct ==
        {
            const int jq   = tid & 3;
            const int tile = tid >> 2;
            const int grp  = tile >> 5;
            const int tt   = tile & 31;
            const int c0   = (tt >> 4) * 4;
            const int i0   = (tt & 15) * 3;
            const float* SIMg = sm + OFF_SIM + grp * SIM_G;
            const float* V = sQKV + (16 * (gp + grp) + 8) * QKV_STRIDE;
            const int jb = jq * 12;

            float w[4][14];
            #pragma unroll
            for (int cc = 0; cc < 4; ++cc) {
                const float* base = sRel + (8 + c0 + cc) * REL_STRIDE + (i0 - jb + 36);
                #pragma unroll
                for (int t = 0; t < 14; ++t) w[cc][t] = base[t];
            }

            float acc[4][3];
            #pragma unroll
            for (int cc = 0; cc < 4; ++cc)
                #pragma unroll
                for (int ii = 0; ii < 3; ++ii) acc[cc][ii] = 0.f;

            #pragma unroll
            for (int jj = 0; jj < 12; ++jj) {
                const int j = jb + jj;
                const float s0 = SIMg[i0 * SIM_STRIDE + j];
                const float s1 = SIMg[(i0 + 1) * SIM_STRIDE + j];
                const float s2 = SIMg[(i0 + 2) * SIM_STRIDE + j];
                #pragma unroll
                for (int cc = 0; cc < 4; ++cc) {
                    const float vv = V[(c0 + cc) * QKV_STRIDE + j];
                    acc[cc][0] += s0 * (vv + w[cc][11 - jj]);
                    acc[cc][1] += s1 * (vv + w[cc][12 - jj]);
                    acc[cc][2] += s2 * (vv + w[cc][13 - jj]);
                }
            }
            #pragma unroll
            for (int cc = 0; cc < 4; ++cc)
                #pragma unroll
                for (int ii = 0; ii < 3; ++ii) {
                    acc[cc][ii] += __shfl_xor_sync(0xffffffffu, acc[cc][ii], 1);
                    acc[cc][ii] += __shfl_xor_sync(0xffffffffu, acc[cc][ii], 2);
                }
            const int c = c0 + jq;
            float* op = out + ((i0 * KS + wi) * KS + li) * 64 + 8 * (gp + grp) + c;
            #pragma unroll
            for (int ii = 0; ii < 3; ++ii) {
                const float av = (jq == 0) ? acc[0][ii] :
                                 (jq == 1) ? acc[1][ii] :
                                 (jq == 2) ? acc[2][ii] : acc[3][ii];
                const int i = i0 + ii;
                op[ii * OUT_PLANE_STRIDE] = av * sGO[i] + sBO[i];
            }
        }
        // no barrier: next pass's qr/kr writes only QR/KR (disjoint from SIM),
        // and its qk-barrier orders SIM re-writes after all sv reads.
    }
}

extern "C" void kernel_launch(void* const* d_in, const int* in_sizes, int n_in,
                              void* d_out, int out_size) {
    (void)in_sizes; (void)n_in; (void)out_size;
    cudaFuncSetAttribute(axial_kernel, cudaFuncAttributeMaxDynamicSharedMemorySize, SMEM_BYTES);
    axial_kernel<<<KS * KS, NT, SMEM_BYTES>>>(
        (const float*)d_in[0], (const float*)d_in[1], (const float*)d_in[2],
        (const float*)d_in[3], (const float*)d_in[4], (const float*)d_in[5],
        (const float*)d_in[6], (const float*)d_in[7], (const float*)d_in[8],
        (float*)d_out);
}

// round 16
// speedup vs baseline: 1.1288x; 1.1288x over previous
#include <cuda_runtime.h>

#define KS 48
#define NT 256

typedef unsigned long long ull;

// strides (floats)
constexpr int SX_STRIDE  = 50;   // X[c][h]
constexpr int W_STRIDE   = 65;   // W[o][c]
constexpr int QKV_STRIDE = 49;   // QKV[o][h]
constexpr int REL_STRIDE = 97;   // rel[c][d]
constexpr int QK_STRIDE  = 50;   // QR/KR [48][50]  (even: ull loads)
constexpr int SIM_STRIDE = 51;   // SIM   [48][51]

constexpr int QK_G  = 48 * QK_STRIDE + 16;  // 2416: ≡16 mod 32
constexpr int SIM_G = 48 * SIM_STRIDE;      // 2448

constexpr int OFF_QKV = 0;                              // 6272
constexpr int OFF_REL = OFF_QKV + 128 * QKV_STRIDE;     // +1552
constexpr int OFF_PAR = OFF_REL + 16 * REL_STRIDE;      // +288
constexpr int OFF_SCR = OFF_PAR + 6 * 48;               // 8112
constexpr int OFF_X   = OFF_SCR;
constexpr int OFF_W   = OFF_X + 64 * SX_STRIDE;
constexpr int OFF_QR  = OFF_SCR;
constexpr int OFF_KR  = OFF_QR + 2 * QK_G;
constexpr int OFF_SIM = OFF_KR + 2 * QK_G;
constexpr int SCR_FLOATS  = 4 * QK_G + 2 * SIM_G;        // 14560 > 11520 (X+W)
constexpr int SMEM_FLOATS = OFF_SCR + SCR_FLOATS;        // 22672
constexpr int SMEM_BYTES  = SMEM_FLOATS * 4;             // 90688 B -> 2 CTAs/SM

constexpr int OUT_PLANE_STRIDE = KS * KS * 64;           // i-stride in out

__device__ __forceinline__ ull dupf(float v) {
    ull r; unsigned u = __float_as_uint(v);
    asm("mov.b64 %0, {%1, %1};" : "=l"(r) : "r"(u));
    return r;
}
__device__ __forceinline__ void ffma2(ull& d, ull a, ull b) {
    asm("fma.rn.f32x2 %0, %1, %2, %0;" : "+l"(d) : "l"(a), "l"(b));
}
__device__ __forceinline__ float f2lo(ull v) { return __uint_as_float((unsigned)(v & 0xffffffffull)); }
__device__ __forceinline__ float f2hi(ull v) { return __uint_as_float((unsigned)(v >> 32)); }

__global__ void __launch_bounds__(NT, 2) axial_kernel(
    const float* __restrict__ x,      const float* __restrict__ w_qkv,
    const float* __restrict__ relv,
    const float* __restrict__ g_qkv,  const float* __restrict__ b_qkv,
    const float* __restrict__ g_sim,  const float* __restrict__ b_sim,
    const float* __restrict__ g_out,  const float* __restrict__ b_out,
    float* __restrict__ out)
{
    extern __shared__ float sm[];
    float* sX   = sm + OFF_X;
    float* sW   = sm + OFF_W;
    float* sQKV = sm + OFF_QKV;
    float* sRel = sm + OFF_REL;
    float* sGQ  = sm + OFF_PAR;
    float* sBQ  = sGQ + 48; float* sGS = sBQ + 48; float* sBS = sGS + 48;
    float* sGO  = sBS + 48; float* sBO = sGO + 48;

    const int tid = threadIdx.x;
    const int blk = blockIdx.x;
    const int wi = blk / KS, li = blk % KS;

    // ---- load X (as [c][h]), W, relative, BN params ----
    for (int idx = tid; idx < KS * 64; idx += NT) {
        const int h = idx >> 6, c = idx & 63;
        sX[c * SX_STRIDE + h] = x[((h * KS + wi) * KS + li) * 64 + c];
    }
    for (int idx = tid; idx < 128 * 64; idx += NT)
        sW[(idx >> 6) * W_STRIDE + (idx & 63)] = w_qkv[idx];
    for (int idx = tid; idx < 16 * 95; idx += NT)
        sRel[(idx / 95) * REL_STRIDE + (idx % 95)] = relv[idx];
    if (tid < KS) {
        const float inv = rsqrtf(1.001f);
        sGQ[tid] = g_qkv[tid] * inv; sBQ[tid] = b_qkv[tid];
        sGS[tid] = g_sim[tid] * inv; sBS[tid] = 3.0f * b_sim[tid];
        sGO[tid] = g_out[tid] * inv; sBO[tid] = 2.0f * b_out[tid];
    }
    __syncthreads();

    // ---- QKV = BN(W @ X): 128x48, 8o x 6h tiles on 128 threads ----
    if (tid < 128) {
        const int o0 = (tid >> 3) * 8;
        const int h0 = (tid & 7) * 6;
        ull a[8][3];
        #pragma unroll
        for (int q = 0; q < 8; ++q)
            #pragma unroll
            for (int p = 0; p < 3; ++p) a[q][p] = 0ull;
        const float* xrow = sX + h0;
        #pragma unroll 2
        for (int c = 0; c < 64; ++c) {
            const ull* xp = reinterpret_cast<const ull*>(xrow + c * SX_STRIDE);
            const ull x01 = xp[0], x23 = xp[1], x45 = xp[2];
            #pragma unroll
            for (int q = 0; q < 8; ++q) {
                const ull wd = dupf(sW[(o0 + q) * W_STRIDE + c]);
                ffma2(a[q][0], wd, x01);
                ffma2(a[q][1], wd, x23);
                ffma2(a[q][2], wd, x45);
            }
        }
        float gg[6], bb[6];
        #pragma unroll
        for (int p = 0; p < 6; ++p) { gg[p] = sGQ[h0 + p]; bb[p] = sBQ[h0 + p]; }
        #pragma unroll
        for (int q = 0; q < 8; ++q) {
            float* dst = sQKV + (o0 + q) * QKV_STRIDE + h0;
            #pragma unroll
            for (int p = 0; p < 3; ++p) {
                dst[2 * p]     = f2lo(a[q][p]) * gg[2 * p]     + bb[2 * p];
                dst[2 * p + 1] = f2hi(a[q][p]) * gg[2 * p + 1] + bb[2 * p + 1];
            }
        }
    }
    __syncthreads();

    // ---- 4 passes, 2 groups each (3 barriers per pass) ----
    for (int gp = 0; gp < 8; gp += 2) {

        // == qr/kr: 1536 sextet tasks (i = il + 8k), exactly 6 per thread ==
        for (int q = tid; q < 1536; q += NT) {
            if (q < 768) {
                const int grp = q / 384; const int r = q - grp * 384;
                const int m = r >> 3, il = r & 7;
                const float* Q = sQKV + (16 * (gp + grp)) * QKV_STRIDE;
                float* QRg = sm + OFF_QR + grp * QK_G;
                float a0 = 0.f, a1 = 0.f, a2 = 0.f, a3 = 0.f, a4 = 0.f, a5 = 0.f;
                #pragma unroll
                for (int c = 0; c < 4; ++c) {
                    const float qc = Q[c * QKV_STRIDE + m];
                    const float* rl = sRel + c * REL_STRIDE + (m - il + 47);
                    a0 += qc * rl[0];   a1 += qc * rl[-8];
                    a2 += qc * rl[-16]; a3 += qc * rl[-24];
                    a4 += qc * rl[-32]; a5 += qc * rl[-40];
                }
                float* d = QRg + m * QK_STRIDE + il;
                d[0] = a0;  d[8] = a1;  d[16] = a2;
                d[24] = a3; d[32] = a4; d[40] = a5;
            } else {
                int r = q - 768; const int grp = r / 384; r -= grp * 384;
                const int j = r >> 3, ml = r & 7;
                const float* Kp = sQKV + (16 * (gp + grp) + 4) * QKV_STRIDE;
                float* KRg = sm + OFF_KR + grp * QK_G;
                float a0 = 0.f, a1 = 0.f, a2 = 0.f, a3 = 0.f, a4 = 0.f, a5 = 0.f;
                #pragma unroll
                for (int c = 0; c < 4; ++c) {
                    const float kc = Kp[c * QKV_STRIDE + j];
                    const float* rl = sRel + (4 + c) * REL_STRIDE + (j - ml + 47);
                    a0 += kc * rl[0];   a1 += kc * rl[-8];
                    a2 += kc * rl[-16]; a3 += kc * rl[-24];
                    a4 += kc * rl[-32]; a5 += kc * rl[-40];
                }
                float* d = KRg + ml * QK_STRIDE + j;
                d[0]               = a0;
                d[8 * QK_STRIDE]   = a1;
                d[16 * QK_STRIDE]  = a2;
                d[24 * QK_STRIDE]  = a3;
                d[32 * QK_STRIDE]  = a4;
                d[40 * QK_STRIDE]  = a5;
            }
        }
        __syncthreads();

        // == qk: 6x6 tiles; balanced warp map; m-split lane pairs, shfl reduce ==
        {
            const int mhalf = tid & 1;
            const int tile  = tid >> 1;          // 0..127
            const int grp   = tile >> 6;
            const int tt    = tile & 63;
            const int i0    = ((tt & 3)        + ((tt >> 4) & 1) * 4) * 6;
            const int j0    = (((tt >> 2) & 3) + ((tt >> 5) & 1) * 4) * 6;
            const float* QRg = sm + OFF_QR + grp * QK_G;
            const float* KRg = sm + OFF_KR + grp * QK_G;
            float* SIMg = sm + OFF_SIM + grp * SIM_G;

            ull acc[3][6];
            #pragma unroll
            for (int p = 0; p < 3; ++p)
                #pragma unroll
                for (int jj = 0; jj < 6; ++jj) acc[p][jj] = 0ull;

            const int mbase = mhalf * 24;
            #pragma unroll 4
            for (int mm = 0; mm < 24; ++mm) {
                const float* qp = QRg + (mbase + mm) * QK_STRIDE + i0;
                const ull q01 = reinterpret_cast<const ull*>(qp)[0];
                const ull q23 = reinterpret_cast<const ull*>(qp)[1];
                const ull q45 = reinterpret_cast<const ull*>(qp)[2];
                const float* kp = KRg + (mbase + mm) * QK_STRIDE + j0;
                const ull k01 = reinterpret_cast<const ull*>(kp)[0];
                const ull k23 = reinterpret_cast<const ull*>(kp)[1];
                const ull k45 = reinterpret_cast<const ull*>(kp)[2];
                const ull kd[6] = {dupf(f2lo(k01)), dupf(f2hi(k01)),
                                   dupf(f2lo(k23)), dupf(f2hi(k23)),
                                   dupf(f2lo(k45)), dupf(f2hi(k45))};
                #pragma unroll
                for (int jj = 0; jj < 6; ++jj) {
                    ffma2(acc[0][jj], q01, kd[jj]);
                    ffma2(acc[1][jj], q23, kd[jj]);
                    ffma2(acc[2][jj], q45, kd[jj]);
                }
            }
            float full[6][6];
            #pragma unroll
            for (int p = 0; p < 3; ++p)
                #pragma unroll
                for (int jj = 0; jj < 6; ++jj) {
                    const ull other = __shfl_xor_sync(0xffffffffu, acc[p][jj], 1);
                    full[2 * p][jj]     = f2lo(acc[p][jj]) + f2lo(other);
                    full[2 * p + 1][jj] = f2hi(acc[p][jj]) + f2hi(other);
                }
            const int rbase = mhalf * 3;
            #pragma unroll
            for (int rr = 0; rr < 3; ++rr) {
                const int i = i0 + rbase + rr;
                const ull* qrp = reinterpret_cast<const ull*>(QRg + i * QK_STRIDE + j0);
                const ull* krp = reinterpret_cast<const ull*>(KRg + i * QK_STRIDE + j0);
                const ull qr01 = qrp[0], qr23 = qrp[1], qr45 = qrp[2];
                const ull kr01 = krp[0], kr23 = krp[1], kr45 = krp[2];
                const float qv[6] = {f2lo(qr01), f2hi(qr01), f2lo(qr23),
                                     f2hi(qr23), f2lo(qr45), f2hi(qr45)};
                const float kv[6] = {f2lo(kr01), f2hi(kr01), f2lo(kr23),
                                     f2hi(kr23), f2lo(kr45), f2hi(kr45)};
                float* srow = SIMg + i * SIM_STRIDE + j0;
                #pragma unroll
                for (int jj = 0; jj < 6; ++jj) {
                    const int j = j0 + jj;
                    const float v = full[rbase + rr][jj] + qv[jj] + kv[jj];
                    srow[jj] = v * sGS[j] + sBS[j];
                }
            }
        }
        __syncthreads();

        // == softmax: 96 rows as 48 pairs; 16 lanes/row, 3 j/lane; 2-wide ILP ==
        {
            const int lane = tid & 31, wp = tid >> 5;
            const int half16 = lane >> 4;
            const int jb = (lane & 15) * 3;
            #pragma unroll
            for (int rp = wp; rp < 48; rp += 16) {
                float* rowA = sm + OFF_SIM + (2 * rp + half16) * SIM_STRIDE;
                float* rowB = sm + OFF_SIM + (2 * (rp + 8) + half16) * SIM_STRIDE;
                const float a0 = rowA[jb], a1 = rowA[jb + 1], a2 = rowA[jb + 2];
                const float b0 = rowB[jb], b1 = rowB[jb + 1], b2 = rowB[jb + 2];
                float mxA = fmaxf(a0, fmaxf(a1, a2));
                float mxB = fmaxf(b0, fmaxf(b1, b2));
                #pragma unroll
                for (int off = 1; off < 16; off <<= 1) {
                    mxA = fmaxf(mxA, __shfl_xor_sync(0xffffffffu, mxA, off));
                    mxB = fmaxf(mxB, __shfl_xor_sync(0xffffffffu, mxB, off));
                }
                const float eA0 = __expf(a0 - mxA), eA1 = __expf(a1 - mxA), eA2 = __expf(a2 - mxA);
                const float eB0 = __expf(b0 - mxB), eB1 = __expf(b1 - mxB), eB2 = __expf(b2 - mxB);
                float sA = eA0 + eA1 + eA2;
                float sB = eB0 + eB1 + eB2;
                #pragma unroll
                for (int off = 1; off < 16; off <<= 1) {
                    sA += __shfl_xor_sync(0xffffffffu, sA, off);
                    sB += __shfl_xor_sync(0xffffffffu, sB, off);
                }
                const float rA = __fdividef(1.0f, sA);
                const float rB = __fdividef(1.0f, sB);
                rowA[jb] = eA0 * rA; rowA[jb + 1] = eA1 * rA; rowA[jb + 2] = eA2 * rA;
                rowB[jb] = eB0 * rB; rowB[jb + 1] = eB1 * rB; rowB[jb + 2] = eB2 * rB;
            }
        }
        __syncthreads();

        // == sv: 4c x 3i tiles x 4 j-splits; rel windows preloaded; STG direct ==
        {
            const int jq   = tid & 3;
            const int tile = tid >> 2;           // 0..63
            const int grp  = tile >> 5;
            const int tt   = tile & 31;
            const int c0   = (tt >> 4) * 4;
            const int i0   = (tt & 15) * 3;
            const float* SIMg = sm + OFF_SIM + grp * SIM_G;
            const float* V = sQKV + (16 * (gp + grp) + 8) * QKV_STRIDE;
            const int jb = jq * 12;

            float w[4][14];
            #pragma unroll
            for (int cc = 0; cc < 4; ++cc) {
                const float* base = sRel + (8 + c0 + cc) * REL_STRIDE + (i0 - jb + 36);
                #pragma unroll
                for (int t = 0; t < 14; ++t) w[cc][t] = base[t];
            }

            float acc[4][3];
            #pragma unroll
            for (int cc = 0; cc < 4; ++cc)
                #pragma unroll
                for (int ii = 0; ii < 3; ++ii) acc[cc][ii] = 0.f;

            #pragma unroll
            for (int jj = 0; jj < 12; ++jj) {
                const int j = jb + jj;
                const float s0 = SIMg[i0 * SIM_STRIDE + j];
                const float s1 = SIMg[(i0 + 1) * SIM_STRIDE + j];
                const float s2 = SIMg[(i0 + 2) * SIM_STRIDE + j];
                #pragma unroll
                for (int cc = 0; cc < 4; ++cc) {
                    const float vv = V[(c0 + cc) * QKV_STRIDE + j];
                    acc[cc][0] += s0 * (vv + w[cc][11 - jj]);
                    acc[cc][1] += s1 * (vv + w[cc][12 - jj]);
                    acc[cc][2] += s2 * (vv + w[cc][13 - jj]);
                }
            }
            #pragma unroll
            for (int cc = 0; cc < 4; ++cc)
                #pragma unroll
                for (int ii = 0; ii < 3; ++ii) {
                    acc[cc][ii] += __shfl_xor_sync(0xffffffffu, acc[cc][ii], 1);
                    acc[cc][ii] += __shfl_xor_sync(0xffffffffu, acc[cc][ii], 2);
                }
            const int c = c0 + jq;
            float* op = out + ((i0 * KS + wi) * KS + li) * 64 + 8 * (gp + grp) + c;
            #pragma unroll
            for (int ii = 0; ii < 3; ++ii) {
                const float av = (jq == 0) ? acc[0][ii] :
                                 (jq == 1) ? acc[1][ii] :
                                 (jq == 2) ? acc[2][ii] : acc[3][ii];
                const int i = i0 + ii;
                op[ii * OUT_PLANE_STRIDE] = av * sGO[i] + sBO[i];
            }
        }
        // no barrier: next pass's qr/kr writes only QR/KR (disjoint from SIM),
        // and its qk-barrier orders SIM re-writes after all sv reads.
    }
}

extern "C" void kernel_launch(void* const* d_in, const int* in_sizes, int n_in,
                              void* d_out, int out_size) {
    (void)in_sizes; (void)n_in; (void)out_size;
    cudaFuncSetAttribute(axial_kernel, cudaFuncAttributeMaxDynamicSharedMemorySize, SMEM_BYTES);
    axial_kernel<<<KS * KS, NT, SMEM_BYTES>>>(
        (const float*)d_in[0], (const float*)d_in[1], (const float*)d_in[2],
        (const float*)d_in[3], (const float*)d_in[4], (const float*)d_in[5],
        (const float*)d_in[6], (const float*)d_in[7], (const float*)d_in[8],
        (float*)d_out);
}